// round 1
// baseline (speedup 1.0000x reference)
#include <cuda_runtime.h>
#include <math.h>

// Problem constants
#define BATCH 65536
#define IN_F  2048
#define GROUP 256            // max-reduction group size (rows per output)
#define THREADS 1024         // 32 warps per CTA
#define ROWS_PER_WARP (GROUP / (THREADS / 32))   // 8
#define VEC_PER_ROW (IN_F / 4)                   // 512 float4
#define VEC_PER_LANE (VEC_PER_ROW / 32)          // 16 float4 per lane per row

__global__ __launch_bounds__(THREADS, 2)
void fused_gemv_gelu_max_kernel(const float* __restrict__ x,
                                const float* __restrict__ w,
                                const float* __restrict__ bias,
                                float* __restrict__ out)
{
    __shared__ float s_warp_max[32];

    const int tid  = threadIdx.x;
    const int warp = tid >> 5;
    const int lane = tid & 31;
    const int groupBase = blockIdx.x * GROUP;

    // Zero the poisoned output slots this block owns (all but index 0 of group).
    if (tid >= 1 && tid < GROUP) {
        out[groupBase + tid] = 0.0f;
    }

    // Hold the weight vector in registers: each lane keeps 16 float4
    // (lane strided). Reused across all 8 rows this warp processes.
    const float4* __restrict__ w4 = reinterpret_cast<const float4*>(w);
    float4 wr[VEC_PER_LANE];
    #pragma unroll
    for (int i = 0; i < VEC_PER_LANE; i++) {
        wr[i] = w4[lane + i * 32];
    }

    const float b = bias[0];

    float mx = -INFINITY;

    #pragma unroll
    for (int r = 0; r < ROWS_PER_WARP; r++) {
        const int row = groupBase + warp * ROWS_PER_WARP + r;
        const float4* __restrict__ xr =
            reinterpret_cast<const float4*>(x + (size_t)row * IN_F);

        float sum = 0.0f;
        #pragma unroll
        for (int i = 0; i < VEC_PER_LANE; i++) {
            float4 v = xr[lane + i * 32];
            sum = fmaf(v.x, wr[i].x, sum);
            sum = fmaf(v.y, wr[i].y, sum);
            sum = fmaf(v.z, wr[i].z, sum);
            sum = fmaf(v.w, wr[i].w, sum);
        }

        // Warp all-reduce sum (butterfly: all lanes end with the full sum)
        #pragma unroll
        for (int o = 16; o > 0; o >>= 1)
            sum += __shfl_xor_sync(0xFFFFFFFFu, sum, o);

        // epilogue: +bias, /POOL(=4), tanh-GELU, *SCALE(=2)
        float y = sum + b;
        float p = y * 0.25f;
        float inner = 0.7978845608f * (p + 0.044715f * p * p * p);
        float g = 0.5f * p * (1.0f + tanhf(inner));
        float s = g * 2.0f;
        mx = fmaxf(mx, s);
    }

    // Block max reduce: one value per warp -> warp 0 reduces 32 values.
    if (lane == 0) s_warp_max[warp] = mx;
    __syncthreads();

    if (warp == 0) {
        float m = s_warp_max[lane];
        #pragma unroll
        for (int o = 16; o > 0; o >>= 1)
            m = fmaxf(m, __shfl_xor_sync(0xFFFFFFFFu, m, o));
        if (lane == 0) out[groupBase] = m;
    }
}

extern "C" void kernel_launch(void* const* d_in, const int* in_sizes, int n_in,
                              void* d_out, int out_size)
{
    const float* x    = (const float*)d_in[0];   // [65536, 2048]
    const float* w    = (const float*)d_in[1];   // [1, 2048]
    const float* bias = (const float*)d_in[2];   // [1]
    float* out = (float*)d_out;                  // [65536]

    const int numGroups = BATCH / GROUP;         // 256 blocks
    fused_gemv_gelu_max_kernel<<<numGroups, THREADS>>>(x, w, bias, out);
}

// round 2
// speedup vs baseline: 1.0841x; 1.0841x over previous
#include <cuda_runtime.h>
#include <math.h>

// Problem constants
#define BATCH 65536
#define IN_F  2048
#define GROUP 256            // max-reduction group size (rows per output)
#define THREADS 1024         // 32 warps per CTA
#define ROWS_PER_WARP (GROUP / (THREADS / 32))   // 8
#define VEC_PER_ROW (IN_F / 4)                   // 512 float4
#define VEC_PER_LANE (VEC_PER_ROW / 32)          // 16 float4 per lane per row

__global__ __launch_bounds__(THREADS, 2)
void fused_gemv_gelu_max_kernel(const float* __restrict__ x,
                                const float* __restrict__ w,
                                const float* __restrict__ bias,
                                float* __restrict__ out)
{
    // Weight vector cached in shared memory: 2048 floats = 8 KB.
    __shared__ float4 sw[VEC_PER_ROW];
    __shared__ float s_warp_max[32];

    const int tid  = threadIdx.x;
    const int warp = tid >> 5;
    const int lane = tid & 31;
    const int groupBase = blockIdx.x * GROUP;

    // Cooperative load of weights into smem (512 float4 by 1024 threads).
    if (tid < VEC_PER_ROW) {
        sw[tid] = reinterpret_cast<const float4*>(w)[tid];
    }

    // Zero the poisoned output slots this block owns (all but index 0 of group).
    if (tid >= 1 && tid < GROUP) {
        out[groupBase + tid] = 0.0f;
    }

    __syncthreads();

    const float b = bias[0];

    float mx = -INFINITY;

    #pragma unroll
    for (int r = 0; r < ROWS_PER_WARP; r++) {
        const int row = groupBase + warp * ROWS_PER_WARP + r;
        const float4* __restrict__ xr =
            reinterpret_cast<const float4*>(x + (size_t)row * IN_F);

        float sum = 0.0f;
        #pragma unroll
        for (int i = 0; i < VEC_PER_LANE; i++) {
            float4 v  = xr[lane + i * 32];
            float4 wv = sw[lane + i * 32];
            sum = fmaf(v.x, wv.x, sum);
            sum = fmaf(v.y, wv.y, sum);
            sum = fmaf(v.z, wv.z, sum);
            sum = fmaf(v.w, wv.w, sum);
        }

        // Warp all-reduce sum (butterfly)
        #pragma unroll
        for (int o = 16; o > 0; o >>= 1)
            sum += __shfl_xor_sync(0xFFFFFFFFu, sum, o);

        // epilogue: +bias, /POOL(=4), tanh-GELU, *SCALE(=2)
        float y = sum + b;
        float p = y * 0.25f;
        float inner = 0.7978845608f * (p + 0.044715f * p * p * p);
        float g = 0.5f * p * (1.0f + tanhf(inner));
        float s = g * 2.0f;
        mx = fmaxf(mx, s);
    }

    // Block max reduce: one value per warp -> warp 0 reduces 32 values.
    if (lane == 0) s_warp_max[warp] = mx;
    __syncthreads();

    if (warp == 0) {
        float m = s_warp_max[lane];
        #pragma unroll
        for (int o = 16; o > 0; o >>= 1)
            m = fmaxf(m, __shfl_xor_sync(0xFFFFFFFFu, m, o));
        if (lane == 0) out[groupBase] = m;
    }
}

extern "C" void kernel_launch(void* const* d_in, const int* in_sizes, int n_in,
                              void* d_out, int out_size)
{
    const float* x    = (const float*)d_in[0];   // [65536, 2048]
    const float* w    = (const float*)d_in[1];   // [1, 2048]
    const float* bias = (const float*)d_in[2];   // [1]
    float* out = (float*)d_out;                  // [65536]

    const int numGroups = BATCH / GROUP;         // 256 blocks
    fused_gemv_gelu_max_kernel<<<numGroups, THREADS>>>(x, w, bias, out);
}

// round 3
// speedup vs baseline: 1.1392x; 1.0508x over previous
#include <cuda_runtime.h>
#include <math.h>

#define BATCH 65536
#define IN_F  2048
#define GROUP 256              // rows per max-group / per CTA
#define THREADS 1024           // 32 warps
#define ROWS_PER_WARP 8        // 32 warps * 8 = 256 rows
#define ROWS_PER_PASS 4        // processed jointly (K-outer)
#define NPASS (ROWS_PER_WARP / ROWS_PER_PASS)   // 2
#define KSTEPS (IN_F / 4 / 32) // 16 float4 per lane per row

__global__ __launch_bounds__(THREADS, 2)
void fused_gemv_gelu_max_kernel(const float* __restrict__ x,
                                const float* __restrict__ w,
                                const float* __restrict__ bias,
                                float* __restrict__ out)
{
    __shared__ float4 sw[IN_F / 4];     // 8 KB weight cache
    __shared__ float s_warp_max[32];

    const int tid  = threadIdx.x;
    const int warp = tid >> 5;
    const int lane = tid & 31;
    const int groupBase = blockIdx.x * GROUP;

    if (tid < IN_F / 4) {
        sw[tid] = reinterpret_cast<const float4*>(w)[tid];
    }
    // Zero the poisoned output slots this block owns (all but index 0).
    if (tid >= 1 && tid < GROUP) {
        out[groupBase + tid] = 0.0f;
    }
    __syncthreads();

    const float b = bias[0];
    float mx = -INFINITY;

    #pragma unroll
    for (int pass = 0; pass < NPASS; pass++) {
        const int row0 = groupBase + warp * ROWS_PER_WARP + pass * ROWS_PER_PASS;
        // One base pointer; per-row offsets are compile-time immediates.
        const float4* __restrict__ xb =
            reinterpret_cast<const float4*>(x + (size_t)row0 * IN_F) + lane;

        float s0 = 0.0f, s1 = 0.0f, s2 = 0.0f, s3 = 0.0f;

        #pragma unroll
        for (int i = 0; i < KSTEPS; i++) {
            const int off = i * 32;
            // 4 independent streaming loads (different rows), then shared weight.
            float4 v0 = __ldcs(xb + off);
            float4 v1 = __ldcs(xb + off + 1 * (IN_F / 4));
            float4 v2 = __ldcs(xb + off + 2 * (IN_F / 4));
            float4 v3 = __ldcs(xb + off + 3 * (IN_F / 4));
            float4 wv = sw[lane + off];

            s0 = fmaf(v0.x, wv.x, s0); s0 = fmaf(v0.y, wv.y, s0);
            s0 = fmaf(v0.z, wv.z, s0); s0 = fmaf(v0.w, wv.w, s0);
            s1 = fmaf(v1.x, wv.x, s1); s1 = fmaf(v1.y, wv.y, s1);
            s1 = fmaf(v1.z, wv.z, s1); s1 = fmaf(v1.w, wv.w, s1);
            s2 = fmaf(v2.x, wv.x, s2); s2 = fmaf(v2.y, wv.y, s2);
            s2 = fmaf(v2.z, wv.z, s2); s2 = fmaf(v2.w, wv.w, s2);
            s3 = fmaf(v3.x, wv.x, s3); s3 = fmaf(v3.y, wv.y, s3);
            s3 = fmaf(v3.z, wv.z, s3); s3 = fmaf(v3.w, wv.w, s3);
        }

        // 4 interleaved butterfly all-reduces (independent chains pipeline).
        #pragma unroll
        for (int o = 16; o > 0; o >>= 1) {
            s0 += __shfl_xor_sync(0xFFFFFFFFu, s0, o);
            s1 += __shfl_xor_sync(0xFFFFFFFFu, s1, o);
            s2 += __shfl_xor_sync(0xFFFFFFFFu, s2, o);
            s3 += __shfl_xor_sync(0xFFFFFFFFu, s3, o);
        }

        // epilogue (all lanes compute identically; no divergence):
        // +bias, /4, tanh-GELU, *2, max
        float sums[4] = {s0, s1, s2, s3};
        #pragma unroll
        for (int r = 0; r < 4; r++) {
            float p = (sums[r] + b) * 0.25f;
            float inner = 0.7978845608f * (p + 0.044715f * p * p * p);
            float g = 0.5f * p * (1.0f + tanhf(inner));
            mx = fmaxf(mx, g * 2.0f);
        }
    }

    // Block max reduce.
    if (lane == 0) s_warp_max[warp] = mx;
    __syncthreads();

    if (warp == 0) {
        float m = s_warp_max[lane];
        #pragma unroll
        for (int o = 16; o > 0; o >>= 1)
            m = fmaxf(m, __shfl_xor_sync(0xFFFFFFFFu, m, o));
        if (lane == 0) out[groupBase] = m;
    }
}

extern "C" void kernel_launch(void* const* d_in, const int* in_sizes, int n_in,
                              void* d_out, int out_size)
{
    const float* x    = (const float*)d_in[0];   // [65536, 2048]
    const float* w    = (const float*)d_in[1];   // [1, 2048]
    const float* bias = (const float*)d_in[2];   // [1]
    float* out = (float*)d_out;                  // [65536]

    fused_gemv_gelu_max_kernel<<<BATCH / GROUP, THREADS>>>(x, w, bias, out);
}

// round 4
// speedup vs baseline: 2.0760x; 1.8224x over previous
#include <cuda_runtime.h>
#include <math.h>

#define BATCH 65536
#define IN_F  2048
#define GROUP 256
#define VEC_ROW (IN_F / 4)        // 512 float4 per row
#define KSTEPS  (VEC_ROW / 32)    // 16 float4 per lane per row
#define NSM 152
#define CHUNK 4                   // rows per work unit
#define NCHUNKS (BATCH / CHUNK)   // 16384

// ---------------- Phase 1: balanced persistent GEMV + GELU epilogue ---------
__global__ __launch_bounds__(1024, 1)
void gemv_phase1(const float* __restrict__ x,
                 const float* __restrict__ w,
                 const float* __restrict__ bias,
                 float* __restrict__ out)
{
    __shared__ float4 sw[VEC_ROW];   // 8 KB weight cache

    const int tid  = threadIdx.x;
    const int warp = tid >> 5;
    const int lane = tid & 31;

    if (tid < VEC_ROW) sw[tid] = reinterpret_cast<const float4*>(w)[tid];
    __syncthreads();

    const float b = bias[0];

    // Contiguous chunk span per CTA: 107 or 108 chunks (16384 over 152 CTAs).
    const int per = NCHUNKS / NSM;          // 107
    const int rem = NCHUNKS % NSM;          // 120
    const int bx  = blockIdx.x;
    const int begin = bx * per + (bx < rem ? bx : rem);
    const int count = per + (bx < rem ? 1 : 0);

    for (int ci = warp; ci < count; ci += 32) {
        const int row0 = (begin + ci) * CHUNK;
        const float4* __restrict__ xb =
            reinterpret_cast<const float4*>(x + (size_t)row0 * IN_F) + lane;

        float s0 = 0.f, s1 = 0.f, s2 = 0.f, s3 = 0.f;

        // Double-buffered: 8 LDG.128 in flight per warp.
        float4 a0 = __ldcs(xb);
        float4 a1 = __ldcs(xb + 1 * VEC_ROW);
        float4 a2 = __ldcs(xb + 2 * VEC_ROW);
        float4 a3 = __ldcs(xb + 3 * VEC_ROW);

        #pragma unroll
        for (int i = 0; i < KSTEPS; i++) {
            float4 b0, b1, b2, b3;
            if (i < KSTEPS - 1) {
                const int off = (i + 1) * 32;
                b0 = __ldcs(xb + off);
                b1 = __ldcs(xb + off + 1 * VEC_ROW);
                b2 = __ldcs(xb + off + 2 * VEC_ROW);
                b3 = __ldcs(xb + off + 3 * VEC_ROW);
            }
            float4 wv = sw[lane + i * 32];
            s0 = fmaf(a0.x, wv.x, s0); s0 = fmaf(a0.y, wv.y, s0);
            s0 = fmaf(a0.z, wv.z, s0); s0 = fmaf(a0.w, wv.w, s0);
            s1 = fmaf(a1.x, wv.x, s1); s1 = fmaf(a1.y, wv.y, s1);
            s1 = fmaf(a1.z, wv.z, s1); s1 = fmaf(a1.w, wv.w, s1);
            s2 = fmaf(a2.x, wv.x, s2); s2 = fmaf(a2.y, wv.y, s2);
            s2 = fmaf(a2.z, wv.z, s2); s2 = fmaf(a2.w, wv.w, s2);
            s3 = fmaf(a3.x, wv.x, s3); s3 = fmaf(a3.y, wv.y, s3);
            s3 = fmaf(a3.z, wv.z, s3); s3 = fmaf(a3.w, wv.w, s3);
            a0 = b0; a1 = b1; a2 = b2; a3 = b3;
        }

        // 4 interleaved butterfly all-reduces.
        #pragma unroll
        for (int o = 16; o > 0; o >>= 1) {
            s0 += __shfl_xor_sync(0xFFFFFFFFu, s0, o);
            s1 += __shfl_xor_sync(0xFFFFFFFFu, s1, o);
            s2 += __shfl_xor_sync(0xFFFFFFFFu, s2, o);
            s3 += __shfl_xor_sync(0xFFFFFFFFu, s3, o);
        }

        // Epilogue: +bias, /4, tanh-GELU, *2. Lanes 0..3 each handle one row.
        if (lane < 4) {
            float sum = (lane == 0) ? s0 : (lane == 1) ? s1 : (lane == 2) ? s2 : s3;
            float p = (sum + b) * 0.25f;
            float inner = 0.7978845608f * (p + 0.044715f * p * p * p);
            float g = 0.5f * p * (1.0f + tanhf(inner));
            out[row0 + lane] = g * 2.0f;
        }
    }
}

// ---------------- Phase 2: in-place per-group max, zero-fill rest ----------
__global__ __launch_bounds__(GROUP, 8)
void maxpool_phase2(float* __restrict__ out)
{
    __shared__ float sm[8];
    const int g    = blockIdx.x;
    const int t    = threadIdx.x;
    const int warp = t >> 5;
    const int lane = t & 31;

    float v = out[g * GROUP + t];
    #pragma unroll
    for (int o = 16; o > 0; o >>= 1)
        v = fmaxf(v, __shfl_xor_sync(0xFFFFFFFFu, v, o));
    if (lane == 0) sm[warp] = v;
    __syncthreads();

    float m = 0.0f;
    if (t == 0) {
        m = sm[0];
        #pragma unroll
        for (int i = 1; i < 8; i++) m = fmaxf(m, sm[i]);
    }
    __syncthreads();            // all reads of out done before overwrite

    out[g * GROUP + t] = 0.0f;
    __syncthreads();
    if (t == 0) out[g * GROUP] = m;
}

extern "C" void kernel_launch(void* const* d_in, const int* in_sizes, int n_in,
                              void* d_out, int out_size)
{
    const float* x    = (const float*)d_in[0];   // [65536, 2048]
    const float* w    = (const float*)d_in[1];   // [1, 2048]
    const float* bias = (const float*)d_in[2];   // [1]
    float* out = (float*)d_out;                  // [65536]

    gemv_phase1<<<NSM, 1024>>>(x, w, bias, out);
    maxpool_phase2<<<BATCH / GROUP, GROUP>>>(out);
}

// round 5
// speedup vs baseline: 2.0918x; 1.0076x over previous
#include <cuda_runtime.h>
#include <math.h>

#define BATCH 65536
#define IN_F  2048
#define GROUP 256
#define VEC_ROW (IN_F / 4)        // 512 float4 per row
#define KSTEPS  (VEC_ROW / 32)    // 16 float4 per lane per row
#define NSM 152
#define CHUNK 4                   // rows per work unit
#define NCHUNKS (BATCH / CHUNK)   // 16384
#define PF 2                      // prefetch distance (3-stage pipeline)

// float atomic max via signed/unsigned ordering trick (valid for all finite
// floats and -inf init): non-negative -> int max; negative -> uint min.
__device__ __forceinline__ void atomicMaxFloat(float* addr, float v)
{
    if (v >= 0.0f) atomicMax((int*)addr, __float_as_int(v));
    else           atomicMin((unsigned int*)addr, __float_as_uint(v));
}

// ---------------- Phase 0: init output (heads = -inf, rest = 0) ------------
__global__ __launch_bounds__(1024)
void init_out(float* __restrict__ out)
{
    const int i = blockIdx.x * 1024 + threadIdx.x;   // 64 * 1024 = 65536
    out[i] = (i & (GROUP - 1)) ? 0.0f : -INFINITY;
}

// ---------------- Phase 1: persistent GEMV + GELU + atomic group max -------
__global__ __launch_bounds__(1024, 1)
void gemv_phase1(const float* __restrict__ x,
                 const float* __restrict__ w,
                 const float* __restrict__ bias,
                 float* __restrict__ out)
{
    __shared__ float4 sw[VEC_ROW];   // 8 KB weight cache

    const int tid  = threadIdx.x;
    const int warp = tid >> 5;
    const int lane = tid & 31;

    if (tid < VEC_ROW) sw[tid] = reinterpret_cast<const float4*>(w)[tid];
    __syncthreads();

    const float b = bias[0];

    // Contiguous chunk span per CTA: 107 or 108 chunks (16384 over 152 CTAs).
    const int per = NCHUNKS / NSM;          // 107
    const int rem = NCHUNKS % NSM;          // 120
    const int bx  = blockIdx.x;
    const int begin = bx * per + (bx < rem ? bx : rem);
    const int count = per + (bx < rem ? 1 : 0);

    for (int ci = warp; ci < count; ci += 32) {
        const int row0 = (begin + ci) * CHUNK;
        const float4* __restrict__ xb =
            reinterpret_cast<const float4*>(x + (size_t)row0 * IN_F) + lane;

        float s0 = 0.f, s1 = 0.f, s2 = 0.f, s3 = 0.f;

        // 3-stage software pipeline: ~12 LDG.128 in flight per warp.
        float4 buf[PF + 1][4];
        #pragma unroll
        for (int p = 0; p < PF; p++) {
            const int off = p * 32;
            buf[p][0] = __ldcs(xb + off);
            buf[p][1] = __ldcs(xb + off + 1 * VEC_ROW);
            buf[p][2] = __ldcs(xb + off + 2 * VEC_ROW);
            buf[p][3] = __ldcs(xb + off + 3 * VEC_ROW);
        }

        #pragma unroll
        for (int i = 0; i < KSTEPS; i++) {
            if (i + PF < KSTEPS) {
                const int off = (i + PF) * 32;
                const int st  = (i + PF) % (PF + 1);
                buf[st][0] = __ldcs(xb + off);
                buf[st][1] = __ldcs(xb + off + 1 * VEC_ROW);
                buf[st][2] = __ldcs(xb + off + 2 * VEC_ROW);
                buf[st][3] = __ldcs(xb + off + 3 * VEC_ROW);
            }
            const int cu = i % (PF + 1);
            float4 wv = sw[lane + i * 32];
            s0 = fmaf(buf[cu][0].x, wv.x, s0); s0 = fmaf(buf[cu][0].y, wv.y, s0);
            s0 = fmaf(buf[cu][0].z, wv.z, s0); s0 = fmaf(buf[cu][0].w, wv.w, s0);
            s1 = fmaf(buf[cu][1].x, wv.x, s1); s1 = fmaf(buf[cu][1].y, wv.y, s1);
            s1 = fmaf(buf[cu][1].z, wv.z, s1); s1 = fmaf(buf[cu][1].w, wv.w, s1);
            s2 = fmaf(buf[cu][2].x, wv.x, s2); s2 = fmaf(buf[cu][2].y, wv.y, s2);
            s2 = fmaf(buf[cu][2].z, wv.z, s2); s2 = fmaf(buf[cu][2].w, wv.w, s2);
            s3 = fmaf(buf[cu][3].x, wv.x, s3); s3 = fmaf(buf[cu][3].y, wv.y, s3);
            s3 = fmaf(buf[cu][3].z, wv.z, s3); s3 = fmaf(buf[cu][3].w, wv.w, s3);
        }

        // 4 interleaved butterfly all-reduces.
        #pragma unroll
        for (int o = 16; o > 0; o >>= 1) {
            s0 += __shfl_xor_sync(0xFFFFFFFFu, s0, o);
            s1 += __shfl_xor_sync(0xFFFFFFFFu, s1, o);
            s2 += __shfl_xor_sync(0xFFFFFFFFu, s2, o);
            s3 += __shfl_xor_sync(0xFFFFFFFFu, s3, o);
        }

        // Epilogue: lanes 0..3 each compute one row's GELU, reduce chunk max,
        // lane 0 fires one atomic into the group head.
        float v = -INFINITY;
        if (lane < 4) {
            float sum = (lane == 0) ? s0 : (lane == 1) ? s1 : (lane == 2) ? s2 : s3;
            float p = (sum + b) * 0.25f;
            float inner = 0.7978845608f * (p + 0.044715f * p * p * p);
            float g = 0.5f * p * (1.0f + tanhf(inner));
            v = g * 2.0f;
        }
        v = fmaxf(v, __shfl_xor_sync(0xFFFFFFFFu, v, 1));
        v = fmaxf(v, __shfl_xor_sync(0xFFFFFFFFu, v, 2));
        if (lane == 0) {
            atomicMaxFloat(&out[row0 & ~(GROUP - 1)], v);
        }
    }
}

extern "C" void kernel_launch(void* const* d_in, const int* in_sizes, int n_in,
                              void* d_out, int out_size)
{
    const float* x    = (const float*)d_in[0];   // [65536, 2048]
    const float* w    = (const float*)d_in[1];   // [1, 2048]
    const float* bias = (const float*)d_in[2];   // [1]
    float* out = (float*)d_out;                  // [65536]

    init_out<<<BATCH / 1024, 1024>>>(out);
    gemv_phase1<<<NSM, 1024>>>(x, w, bias, out);
}

// round 6
// speedup vs baseline: 2.1764x; 1.0404x over previous
#include <cuda_runtime.h>
#include <math.h>

#define BATCH 65536
#define IN_F  2048
#define GROUP 256
#define VEC_ROW (IN_F / 4)        // 512 float4 per row
#define KSTEPS  (VEC_ROW / 32)    // 16 float4 per lane per row
#define NSM 152
#define CHUNK 4                   // rows per work unit
#define NCHUNKS (BATCH / CHUNK)   // 16384
#define PF 2                      // prefetch distance (3-stage pipeline)
#define NGROUPS (BATCH / GROUP)   // 256

// float atomic max via signed/unsigned ordering trick (valid for all finite
// floats and -inf init): non-negative -> int max; negative -> uint min.
__device__ __forceinline__ void atomicMaxFloat(float* addr, float v)
{
    if (v >= 0.0f) atomicMax((int*)addr, __float_as_int(v));
    else           atomicMin((unsigned int*)addr, __float_as_uint(v));
}

// -------- Phase 0: init ONLY the 256 group heads to -inf (1 KB) ------------
__global__ __launch_bounds__(NGROUPS)
void init_heads(float* __restrict__ out)
{
    out[threadIdx.x * GROUP] = -INFINITY;
}

// ---------------- Phase 1: persistent GEMV + GELU + atomic group max -------
// Also zero-fills all non-head output rows (d_out is poisoned).
__global__ __launch_bounds__(1024, 1)
void gemv_phase1(const float* __restrict__ x,
                 const float* __restrict__ w,
                 const float* __restrict__ bias,
                 float* __restrict__ out)
{
    __shared__ float4 sw[VEC_ROW];   // 8 KB weight cache

    const int tid  = threadIdx.x;
    const int warp = tid >> 5;
    const int lane = tid & 31;

    if (tid < VEC_ROW) sw[tid] = reinterpret_cast<const float4*>(w)[tid];
    __syncthreads();

    const float b = bias[0];

    // Contiguous chunk span per CTA: 107 or 108 chunks (16384 over 152 CTAs).
    const int per = NCHUNKS / NSM;          // 107
    const int rem = NCHUNKS % NSM;          // 120
    const int bx  = blockIdx.x;
    const int begin = bx * per + (bx < rem ? bx : rem);
    const int count = per + (bx < rem ? 1 : 0);

    for (int ci = warp; ci < count; ci += 32) {
        const int row0 = (begin + ci) * CHUNK;
        const float4* __restrict__ xb =
            reinterpret_cast<const float4*>(x + (size_t)row0 * IN_F) + lane;

        float s0 = 0.f, s1 = 0.f, s2 = 0.f, s3 = 0.f;

        // 3-stage software pipeline: ~12 LDG.128 in flight per warp.
        float4 buf[PF + 1][4];
        #pragma unroll
        for (int p = 0; p < PF; p++) {
            const int off = p * 32;
            buf[p][0] = __ldcs(xb + off);
            buf[p][1] = __ldcs(xb + off + 1 * VEC_ROW);
            buf[p][2] = __ldcs(xb + off + 2 * VEC_ROW);
            buf[p][3] = __ldcs(xb + off + 3 * VEC_ROW);
        }

        #pragma unroll
        for (int i = 0; i < KSTEPS; i++) {
            if (i + PF < KSTEPS) {
                const int off = (i + PF) * 32;
                const int st  = (i + PF) % (PF + 1);
                buf[st][0] = __ldcs(xb + off);
                buf[st][1] = __ldcs(xb + off + 1 * VEC_ROW);
                buf[st][2] = __ldcs(xb + off + 2 * VEC_ROW);
                buf[st][3] = __ldcs(xb + off + 3 * VEC_ROW);
            }
            const int cu = i % (PF + 1);
            float4 wv = sw[lane + i * 32];
            s0 = fmaf(buf[cu][0].x, wv.x, s0); s0 = fmaf(buf[cu][0].y, wv.y, s0);
            s0 = fmaf(buf[cu][0].z, wv.z, s0); s0 = fmaf(buf[cu][0].w, wv.w, s0);
            s1 = fmaf(buf[cu][1].x, wv.x, s1); s1 = fmaf(buf[cu][1].y, wv.y, s1);
            s1 = fmaf(buf[cu][1].z, wv.z, s1); s1 = fmaf(buf[cu][1].w, wv.w, s1);
            s2 = fmaf(buf[cu][2].x, wv.x, s2); s2 = fmaf(buf[cu][2].y, wv.y, s2);
            s2 = fmaf(buf[cu][2].z, wv.z, s2); s2 = fmaf(buf[cu][2].w, wv.w, s2);
            s3 = fmaf(buf[cu][3].x, wv.x, s3); s3 = fmaf(buf[cu][3].y, wv.y, s3);
            s3 = fmaf(buf[cu][3].z, wv.z, s3); s3 = fmaf(buf[cu][3].w, wv.w, s3);
        }

        // 4 interleaved butterfly all-reduces.
        #pragma unroll
        for (int o = 16; o > 0; o >>= 1) {
            s0 += __shfl_xor_sync(0xFFFFFFFFu, s0, o);
            s1 += __shfl_xor_sync(0xFFFFFFFFu, s1, o);
            s2 += __shfl_xor_sync(0xFFFFFFFFu, s2, o);
            s3 += __shfl_xor_sync(0xFFFFFFFFu, s3, o);
        }

        // Epilogue: lanes 0..3 compute the 4 row GELUs. Non-head rows are
        // zero-filled with plain stores; the group head gets one atomicMax
        // per chunk. (Head row is row0+0 only when row0 % 256 == 0, so the
        // zero stores never alias the head.)
        float v = -INFINITY;
        if (lane < 4) {
            float sum = (lane == 0) ? s0 : (lane == 1) ? s1 : (lane == 2) ? s2 : s3;
            float p = (sum + b) * 0.25f;
            float inner = 0.7978845608f * (p + 0.044715f * p * p * p);
            float g = 0.5f * p * (1.0f + tanhf(inner));
            v = g * 2.0f;
            const bool isHead = ((row0 & (GROUP - 1)) == 0) && (lane == 0);
            if (!isHead) out[row0 + lane] = 0.0f;
        }
        v = fmaxf(v, __shfl_xor_sync(0xFFFFFFFFu, v, 1));
        v = fmaxf(v, __shfl_xor_sync(0xFFFFFFFFu, v, 2));
        if (lane == 0) {
            atomicMaxFloat(&out[row0 & ~(GROUP - 1)], v);
        }
    }
}

extern "C" void kernel_launch(void* const* d_in, const int* in_sizes, int n_in,
                              void* d_out, int out_size)
{
    const float* x    = (const float*)d_in[0];   // [65536, 2048]
    const float* w    = (const float*)d_in[1];   // [1, 2048]
    const float* bias = (const float*)d_in[2];   // [1]
    float* out = (float*)d_out;                  // [65536]

    init_heads<<<1, NGROUPS>>>(out);
    gemv_phase1<<<NSM, 1024>>>(x, w, bias, out);
}